// round 15
// baseline (speedup 1.0000x reference)
#include <cuda_runtime.h>
#include <cuda_bf16.h>
#include <cstddef>

#define N_NODES 512
#define H 8

// ---------------- device scratch ----------------
__device__ __align__(16) float g_qh[N_NODES * H * 60];
__device__ __align__(16) float g_kh[N_NODES * H * 60];
__device__ __align__(16) float g_A[N_NODES * 9 * 64];
__device__ __align__(16) float g_B[N_NODES * 9 * 64];
__device__ __align__(16) float g_vmT[480 * N_NODES];
__device__ __align__(16) float g_X[(size_t)N_NODES * N_NODES * 64];   // b1 + sh*B[s]
__device__ __align__(16) float g_P[(size_t)H * N_NODES * N_NODES];    // planes [h][r][s]
// fragment-order precomputes
__device__ __align__(16) float g_W2f[4096];            // W2 fragments (8 ksi)
__device__ __align__(16) float g_W1f[2048];            // W1a fragments (4 ksi)
__device__ __align__(16) float g_Af[N_NODES * 1024];   // A[r] fragments (2 ksi)
__device__ __align__(16) float g_Bsf[N_NODES * 1024];  // B[s] fragments (2 ksi)

#define CG1 0.5773502691896258f
#define CG2 0.4472135954999579f
#define ATTN_NORM 0.1889822365046136f
#define RS128 0.08838834764831845f
#define RS64  0.125f
#define RS32  0.17677669529663687f

__device__ __forceinline__ float ftanh(float x) {
    return 1.0f - __fdividef(2.0f, __expf(2.0f * x) + 1.0f);
}

__device__ __forceinline__ float f2tf32f(float x) {
    unsigned u;
    asm("cvt.rna.tf32.f32 %0, %1;" : "=r"(u) : "f"(x));
    return __uint_as_float(u);
}

__device__ __forceinline__ unsigned f2tf32u(float x) {
    unsigned u;
    asm("cvt.rna.tf32.f32 %0, %1;" : "=r"(u) : "f"(x));
    return u;
}

__device__ __forceinline__ void mma_tf32(float* c, const unsigned* a, unsigned b0, unsigned b1) {
    asm volatile(
        "mma.sync.aligned.m16n8k8.row.col.f32.tf32.tf32.f32 "
        "{%0,%1,%2,%3}, {%4,%5,%6,%7}, {%8,%9}, {%0,%1,%2,%3};\n"
        : "+f"(c[0]), "+f"(c[1]), "+f"(c[2]), "+f"(c[3])
        : "r"(a[0]), "r"(a[1]), "r"(a[2]), "r"(a[3]), "r"(b0), "r"(b1));
}

// ================= Kernel 0a: weight fragment precompute (once) =================
__global__ void __launch_bounds__(256) k_prep_w(
    const float* __restrict__ mW1, const float* __restrict__ mW2)
{
    int tid = threadIdx.x;
    for (int i = tid; i < 4096; i += 256) {
        int ksi = i >> 9, rem = i & 511;
        int lane_ = rem >> 4, j = rem & 15;
        int t_ = lane_ & 3, g_ = lane_ >> 2;
        int nt = j >> 1, p = j & 1;
        int k = ksi * 8 + t_ + 4 * p;
        int n = nt * 8 + g_;
        g_W2f[(ksi * 32 + lane_) * 16 + j] = f2tf32f(mW2[k * 64 + n]);
    }
    for (int i = tid; i < 2048; i += 256) {
        int ksi = i >> 9, rem = i & 511;
        int lane_ = rem >> 4, j = rem & 15;
        int t_ = lane_ & 3, g_ = lane_ >> 2;
        int nt = j >> 1, p = j & 1;
        int k = ksi * 8 + t_ + 4 * p;   // < 32
        int n = nt * 8 + g_;
        g_W1f[(ksi * 32 + lane_) * 16 + j] = f2tf32f(mW1[k * 64 + n]);
    }
}

// ================= Kernel 0b: per-node A/B fragment precompute =================
__global__ void __launch_bounds__(256) k_prep_ab()
{
    int n = blockIdx.x;
    int tid = threadIdx.x;
    for (int i = tid; i < 1024; i += 256) {
        int ksi = i >> 9, rem = i & 511;
        int lane_ = rem >> 4, j = rem & 15;
        int t_ = lane_ & 3, g_ = lane_ >> 2;
        int nt = j >> 1, p = j & 1;
        int k = ksi * 8 + t_ + 4 * p;
        int c = nt * 8 + g_;
        float va = (k < 9) ? g_A[(size_t)n * 576 + k * 64 + c] : 0.f;
        g_Af[(size_t)n * 1024 + (ksi * 32 + lane_) * 16 + j] = f2tf32f(va);
        float vb = (k < 9) ? g_B[(size_t)n * 576 + k * 64 + c] : 0.f;
        g_Bsf[(size_t)n * 1024 + (ksi * 32 + lane_) * 16 + j] = f2tf32f(vb);
    }
}

// ================= Kernel 1: per-node precompute =================
__global__ void __launch_bounds__(256) k_node(
    const float* __restrict__ node_feat,
    const float* __restrict__ Wq0, const float* __restrict__ Wq1, const float* __restrict__ Wq2,
    const float* __restrict__ Wk0, const float* __restrict__ Wk1, const float* __restrict__ Wk2,
    const float* __restrict__ Wv0, const float* __restrict__ Wv1, const float* __restrict__ Wv2,
    const float* __restrict__ mW1)
{
    __shared__ float snf[4 * 480];
    int tid = threadIdx.x;
    int n0 = blockIdx.x * 4;

    for (int i = tid; i < 480; i += 256) {
        int nn = i / 120, c4 = i % 120;
        float4 v = *(const float4*)&node_feat[(size_t)(n0 + nn) * 480 + c4 * 4];
        snf[nn * 480 + c4 * 4 + 0] = v.x;
        snf[nn * 480 + c4 * 4 + 1] = v.y;
        snf[nn * 480 + c4 * 4 + 2] = v.z;
        snf[nn * 480 + c4 * 4 + 3] = v.w;
    }
    __syncthreads();

    int gend = 81 * (blockIdx.y + 1);
    for (int g = tid + 81 * blockIdx.y; g < gend; g += 256) {
        int kind, l, m, o, mul, off, mp = 0, stride;
        const float* Wp;
        if (g < 360) {
            int mat = g / 120, gg = g % 120;
            if (gg < 32)      { l = 0; m = 0;              o = gg * 4; }
            else if (gg < 80) { int t = gg - 32; l = 1; o = (t / 3) * 4; m = t % 3; }
            else              { int t = gg - 80; l = 2; o = (t / 5) * 4; m = t % 5; }
            mul = (l == 0) ? 128 : (l == 1) ? 64 : 32;
            off = (l == 0) ? 0 : (l == 1) ? 128 : 320;
            stride = mul;
            if (mat == 0)      Wp = (l == 0) ? Wq0 : (l == 1) ? Wq1 : Wq2;
            else if (mat == 1) Wp = (l == 0) ? Wk0 : (l == 1) ? Wk1 : Wk2;
            else               Wp = (l == 0) ? Wv0 : (l == 1) ? Wv1 : Wv2;
            kind = mat;
        } else {
            int t = g - 360;
            int ab = t / 144, u = t % 144;
            mp = u / 16; o = (u % 16) * 4;
            l = (mp == 0) ? 0 : (mp < 4) ? 1 : 2;
            m = (mp == 0) ? 0 : (mp < 4) ? (mp - 1) : (mp - 4);
            mul = (l == 0) ? 128 : (l == 1) ? 64 : 32;
            off = (l == 0) ? 0 : (l == 1) ? 128 : 320;
            int row = ((l == 0) ? 32 : (l == 1) ? 160 : 224) + ab * 224;
            Wp = mW1 + (size_t)row * 64;
            stride = 64;
            kind = 3 + ab;
        }
        int d = 2 * l + 1;

        float4 a0 = make_float4(0.f,0.f,0.f,0.f), a1 = a0, a2 = a0, a3 = a0;
#pragma unroll 4
        for (int i = 0; i < mul; i++) {
            float4 wv = __ldg((const float4*)&Wp[(size_t)i * stride + o]);
            int col = off + i * d + m;
            float x0 = snf[col], x1 = snf[480 + col], x2 = snf[960 + col], x3 = snf[1440 + col];
            a0.x += x0 * wv.x; a0.y += x0 * wv.y; a0.z += x0 * wv.z; a0.w += x0 * wv.w;
            a1.x += x1 * wv.x; a1.y += x1 * wv.y; a1.z += x1 * wv.z; a1.w += x1 * wv.w;
            a2.x += x2 * wv.x; a2.y += x2 * wv.y; a2.z += x2 * wv.z; a2.w += x2 * wv.w;
            a3.x += x3 * wv.x; a3.y += x3 * wv.y; a3.z += x3 * wv.z; a3.w += x3 * wv.w;
        }

        float rs = (l == 0) ? RS128 : (l == 1) ? RS64 : RS32;
        float cg = (l == 0) ? 1.f   : (l == 1) ? CG1  : CG2;
        float accs[4][4] = {{a0.x,a0.y,a0.z,a0.w},{a1.x,a1.y,a1.z,a1.w},
                            {a2.x,a2.y,a2.z,a2.w},{a3.x,a3.y,a3.z,a3.w}};
#pragma unroll
        for (int nn = 0; nn < 4; nn++) {
            int n = n0 + nn;
#pragma unroll
            for (int oo = 0; oo < 4; oo++) {
                int o_ = o + oo;
                float a = accs[nn][oo];
                if (kind <= 1) {
                    int am = mul >> 3;
                    int hh = o_ / am, oi = o_ % am;
                    int j = (l == 0) ? oi : (l == 1) ? (16 + oi * 3 + m) : (40 + oi * 5 + m);
                    size_t idx = ((size_t)n * H + hh) * 60 + j;
                    if (kind == 0) g_qh[idx] = a * rs * cg * ATTN_NORM;
                    else           g_kh[idx] = a * rs;
                } else if (kind == 2) {
                    int w = (l == 0) ? o_ : (l == 1) ? (128 + o_ * 3 + m) : (320 + o_ * 5 + m);
                    g_vmT[(size_t)w * N_NODES + n] = a * rs;
                } else {
                    float* dst = (kind == 3) ? g_A : g_B;
                    dst[((size_t)n * 9 + mp) * 64 + o_] = a * cg;
                }
            }
        }
    }
}

// ================= Kernel 2: X = b1 + sh*B[s]  (small tf32 GEMM, s-grouped) =================
__global__ void __launch_bounds__(256) k_XB(
    const float* __restrict__ edge_sh, const float* __restrict__ mb1)
{
    __shared__ float shs[128 * 9];     // sh[r][m] tf32 bits
    __shared__ float sBf[2 * 32 * 20]; // B[s] fragments, stride 20
    __shared__ float sb1[64];

    int tid = threadIdx.x;
    int s = blockIdx.x >> 2;
    int r0 = (blockIdx.x & 3) * 128;

    for (int i = tid; i < 1152; i += 256) {
        int r_l = i / 9, m = i % 9;
        shs[r_l * 9 + m] = f2tf32f(__ldg(&edge_sh[((size_t)(r0 + r_l) * 512 + s) * 9 + m]));
    }
    for (int i = tid; i < 256; i += 256) {
        int row = i >> 2, q = i & 3;
        *(float4*)&sBf[row * 20 + q * 4] = ((const float4*)(g_Bsf + (size_t)s * 1024))[i];
    }
    if (tid < 64) sb1[tid] = mb1[tid];
    __syncthreads();

    int w = tid >> 5, lane = tid & 31;
    int g = lane >> 2, t = lane & 3;
    int row0 = w * 16 + g;

    float acc[8][4];
#pragma unroll
    for (int nt = 0; nt < 8; nt++)
#pragma unroll
        for (int cc = 0; cc < 4; cc++) acc[nt][cc] = 0.f;

#pragma unroll
    for (int ksi = 0; ksi < 2; ksi++) {
        int col = ksi * 8 + t;
        unsigned a[4];
        a[0] = (col < 9)     ? __float_as_uint(shs[row0 * 9 + col])           : 0u;
        a[1] = (col < 9)     ? __float_as_uint(shs[(row0 + 8) * 9 + col])     : 0u;
        a[2] = (col + 4 < 9) ? __float_as_uint(shs[row0 * 9 + col + 4])       : 0u;
        a[3] = (col + 4 < 9) ? __float_as_uint(shs[(row0 + 8) * 9 + col + 4]) : 0u;
        const float4* wr = (const float4*)&sBf[(ksi * 32 + lane) * 20];
        float4 w0 = wr[0], w1 = wr[1], w2 = wr[2], w3 = wr[3];
        mma_tf32(acc[0], a, __float_as_uint(w0.x), __float_as_uint(w0.y));
        mma_tf32(acc[1], a, __float_as_uint(w0.z), __float_as_uint(w0.w));
        mma_tf32(acc[2], a, __float_as_uint(w1.x), __float_as_uint(w1.y));
        mma_tf32(acc[3], a, __float_as_uint(w1.z), __float_as_uint(w1.w));
        mma_tf32(acc[4], a, __float_as_uint(w2.x), __float_as_uint(w2.y));
        mma_tf32(acc[5], a, __float_as_uint(w2.z), __float_as_uint(w2.w));
        mma_tf32(acc[6], a, __float_as_uint(w3.x), __float_as_uint(w3.y));
        mma_tf32(acc[7], a, __float_as_uint(w3.z), __float_as_uint(w3.w));
    }

#pragma unroll
    for (int nt = 0; nt < 8; nt++) {
        int col0 = nt * 8 + 2 * t;
        float b0 = sb1[col0], b1v = sb1[col0 + 1];
        *(float2*)&g_X[((size_t)(r0 + row0) * 512 + s) * 64 + col0] =
            make_float2(acc[nt][0] + b0, acc[nt][1] + b1v);
        *(float2*)&g_X[((size_t)(r0 + row0 + 8) * 512 + s) * 64 + col0] =
            make_float2(acc[nt][2] + b0, acc[nt][3] + b1v);
    }
}

// ================= Kernel 3: logits tf32 tensor GEMM: P[h][r][s] = q.k =================
#define LQS 68
__global__ void __launch_bounds__(256) k_logit()
{
    __shared__ float sQ[64 * LQS];   // [r][k], k padded to 64
    __shared__ float sKT[64 * LQS];  // [k][s]
    int tid = threadIdx.x;
    int hh = blockIdx.x >> 6, tile = blockIdx.x & 63;
    int r0 = (tile >> 3) * 64, s0 = (tile & 7) * 64;

    // Q: [r][k] direct, pad k 60..63
    for (int i = tid; i < 960; i += 256) {
        int nl = i / 15, k4 = i % 15;
        float4 v = *(const float4*)&g_qh[((size_t)(r0 + nl) * H + hh) * 60 + k4 * 4];
        float* d = &sQ[nl * LQS + k4 * 4];
        d[0] = f2tf32f(v.x); d[1] = f2tf32f(v.y); d[2] = f2tf32f(v.z); d[3] = f2tf32f(v.w);
    }
    for (int i = tid; i < 256; i += 256) {
        int nl = i >> 2, kk = 60 + (i & 3);
        sQ[nl * LQS + kk] = 0.f;
    }
    // K: transpose into [k][s]
    for (int i = tid; i < 960; i += 256) {
        int nl = i / 15, k4 = i % 15;
        float4 v = *(const float4*)&g_kh[((size_t)(s0 + nl) * H + hh) * 60 + k4 * 4];
        sKT[(k4 * 4 + 0) * LQS + nl] = f2tf32f(v.x);
        sKT[(k4 * 4 + 1) * LQS + nl] = f2tf32f(v.y);
        sKT[(k4 * 4 + 2) * LQS + nl] = f2tf32f(v.z);
        sKT[(k4 * 4 + 3) * LQS + nl] = f2tf32f(v.w);
    }
    for (int i = tid; i < 256; i += 256) {
        int kk = 60 + (i >> 6), nl = i & 63;
        sKT[kk * LQS + nl] = 0.f;
    }
    __syncthreads();

    int w = tid >> 5, lane = tid & 31;
    int g = lane >> 2, t = lane & 3;
    int mt = w & 3, nq = w >> 2;
    int row0 = mt * 16 + g;

    float acc[4][4];
#pragma unroll
    for (int nt = 0; nt < 4; nt++)
#pragma unroll
        for (int cc = 0; cc < 4; cc++) acc[nt][cc] = 0.f;

#pragma unroll
    for (int ksi = 0; ksi < 8; ksi++) {
        int col = ksi * 8 + t;
        unsigned a[4];
        a[0] = __float_as_uint(sQ[row0 * LQS + col]);
        a[1] = __float_as_uint(sQ[(row0 + 8) * LQS + col]);
        a[2] = __float_as_uint(sQ[row0 * LQS + col + 4]);
        a[3] = __float_as_uint(sQ[(row0 + 8) * LQS + col + 4]);
#pragma unroll
        for (int nt = 0; nt < 4; nt++) {
            int n = nq * 32 + nt * 8 + g;
            unsigned b0 = __float_as_uint(sKT[col * LQS + n]);
            unsigned b1 = __float_as_uint(sKT[(col + 4) * LQS + n]);
            mma_tf32(acc[nt], a, b0, b1);
        }
    }

    float* base = g_P + (size_t)hh * (N_NODES * N_NODES);
#pragma unroll
    for (int nt = 0; nt < 4; nt++) {
        int c0 = s0 + nq * 32 + nt * 8 + 2 * t;
        *(float2*)&base[(size_t)(r0 + row0) * 512 + c0] = make_float2(acc[nt][0], acc[nt][1]);
        *(float2*)&base[(size_t)(r0 + row0 + 8) * 512 + c0] = make_float2(acc[nt][2], acc[nt][3]);
    }
}

// ================= Kernel 4: ea GEMM + sh*A GEMM + X add + tanh + GEMM2 + epilogue -> P ====
#define MS 68
#define SMEM_MLP (17480 * 4)

__global__ void __launch_bounds__(256, 3) k_mlp(
    const float* __restrict__ edge_attr, const float* __restrict__ edge_sh,
    const float* __restrict__ mb2,
    const float* __restrict__ mW3, const float* __restrict__ mb3)
{
    extern __shared__ float sm[];
    float* sh1 = sm;                    // [128][MS] : first ea (tf32, cols 0..31), then h1
    float* sW2 = sh1 + 128 * MS;        // [5120] W2 fragments, stride 20
    float* sAf = sW2 + 5120;            // [1024] A[r] fragments, compact stride 16
    float* sW1f = sAf + 1024;           // [2048] W1a fragments, compact stride 16
    float* sW3 = sW1f + 2048;           // [64][8]
    float* sb2 = sW3 + 512;
    float* sb3 = sb2 + 64;

    int tid = threadIdx.x;
    int r = blockIdx.x >> 2;
    int s0 = (blockIdx.x & 3) * 128;

    for (int i = tid; i < 1024; i += 256) {
        int row = i >> 2, q = i & 3;
        *(float4*)&sW2[row * 20 + q * 4] = ((const float4*)g_W2f)[i];
    }
    for (int i = tid; i < 512; i += 256)
        ((float4*)sW1f)[i] = ((const float4*)g_W1f)[i];
    for (int i = tid; i < 256; i += 256)
        ((float4*)sAf)[i] = ((const float4*)(g_Af + (size_t)r * 1024))[i];
    for (int i = tid; i < 512; i += 256) sW3[i] = mW3[i];
    if (tid < 64) sb2[tid] = mb2[tid];
    if (tid < 8)  sb3[tid] = mb3[tid];

    for (int i = tid; i < 1024; i += 256) {
        int s_l = i >> 3, k4 = i & 7;
        float4 v = __ldg((const float4*)&edge_attr[((size_t)r * 512 + s0 + s_l) * 32 + k4 * 4]);
        float4 o;
        o.x = f2tf32f(v.x); o.y = f2tf32f(v.y); o.z = f2tf32f(v.z); o.w = f2tf32f(v.w);
        *(float4*)&sh1[s_l * MS + k4 * 4] = o;
    }
    __syncthreads();

    int w = tid >> 5, lane = tid & 31;
    int g = lane >> 2, t = lane & 3;
    int row0 = w * 16 + g;

    float accA[8][4];
#pragma unroll
    for (int nt = 0; nt < 8; nt++)
#pragma unroll
        for (int cc = 0; cc < 4; cc++) accA[nt][cc] = 0.f;

    // GEMM-ea: ea[128,32] @ W1a[32,64]
#pragma unroll
    for (int ksi = 0; ksi < 4; ksi++) {
        int col = ksi * 8 + t;
        unsigned a[4];
        a[0] = __float_as_uint(sh1[row0 * MS + col]);
        a[1] = __float_as_uint(sh1[(row0 + 8) * MS + col]);
        a[2] = __float_as_uint(sh1[row0 * MS + col + 4]);
        a[3] = __float_as_uint(sh1[(row0 + 8) * MS + col + 4]);
        const float4* wr = (const float4*)&sW1f[(ksi * 32 + lane) * 16];
        float4 w0 = wr[0], w1 = wr[1], w2 = wr[2], w3 = wr[3];
        mma_tf32(accA[0], a, __float_as_uint(w0.x), __float_as_uint(w0.y));
        mma_tf32(accA[1], a, __float_as_uint(w0.z), __float_as_uint(w0.w));
        mma_tf32(accA[2], a, __float_as_uint(w1.x), __float_as_uint(w1.y));
        mma_tf32(accA[3], a, __float_as_uint(w1.z), __float_as_uint(w1.w));
        mma_tf32(accA[4], a, __float_as_uint(w2.x), __float_as_uint(w2.y));
        mma_tf32(accA[5], a, __float_as_uint(w2.z), __float_as_uint(w2.w));
        mma_tf32(accA[6], a, __float_as_uint(w3.x), __float_as_uint(w3.y));
        mma_tf32(accA[7], a, __float_as_uint(w3.z), __float_as_uint(w3.w));
    }

    // GEMM-A: sh[128,9(pad16)] @ A[r][9,64]; a-operands loaded directly from gmem
    {
        const float* shr0 = edge_sh + ((size_t)r * 512 + s0 + row0) * 9;
        const float* shr1 = shr0 + 8 * 9;
#pragma unroll
        for (int ksi = 0; ksi < 2; ksi++) {
            int col = ksi * 8 + t;
            unsigned a[4];
            a[0] = (col < 9)     ? f2tf32u(__ldg(shr0 + col))     : 0u;
            a[1] = (col < 9)     ? f2tf32u(__ldg(shr1 + col))     : 0u;
            a[2] = (col + 4 < 9) ? f2tf32u(__ldg(shr0 + col + 4)) : 0u;
            a[3] = (col + 4 < 9) ? f2tf32u(__ldg(shr1 + col + 4)) : 0u;
            const float4* wr = (const float4*)&sAf[(ksi * 32 + lane) * 16];
            float4 w0 = wr[0], w1 = wr[1], w2 = wr[2], w3 = wr[3];
            mma_tf32(accA[0], a, __float_as_uint(w0.x), __float_as_uint(w0.y));
            mma_tf32(accA[1], a, __float_as_uint(w0.z), __float_as_uint(w0.w));
            mma_tf32(accA[2], a, __float_as_uint(w1.x), __float_as_uint(w1.y));
            mma_tf32(accA[3], a, __float_as_uint(w1.z), __float_as_uint(w1.w));
            mma_tf32(accA[4], a, __float_as_uint(w2.x), __float_as_uint(w2.y));
            mma_tf32(accA[5], a, __float_as_uint(w2.z), __float_as_uint(w2.w));
            mma_tf32(accA[6], a, __float_as_uint(w3.x), __float_as_uint(w3.y));
            mma_tf32(accA[7], a, __float_as_uint(w3.z), __float_as_uint(w3.w));
        }
    }

    // X add + tanh + store h1 fragments
    {
        const float* Xr0 = &g_X[((size_t)r * 512 + s0 + row0) * 64];
        const float* Xr1 = Xr0 + 8 * 64;
#pragma unroll
        for (int nt = 0; nt < 8; nt++) {
            int c0 = nt * 8 + 2 * t;
            float2 x0 = *(const float2*)&Xr0[c0];
            float2 x1 = *(const float2*)&Xr1[c0];
            float h00 = f2tf32f(ftanh(x0.x + accA[nt][0]));
            float h01 = f2tf32f(ftanh(x0.y + accA[nt][1]));
            float h10 = f2tf32f(ftanh(x1.x + accA[nt][2]));
            float h11 = f2tf32f(ftanh(x1.y + accA[nt][3]));
            *(float2*)&sh1[row0 * MS + c0] = make_float2(h00, h01);
            *(float2*)&sh1[(row0 + 8) * MS + c0] = make_float2(h10, h11);
        }
    }
    __syncthreads();

    // GEMM2
    float acc2[8][4];
#pragma unroll
    for (int nt = 0; nt < 8; nt++)
#pragma unroll
        for (int cc = 0; cc < 4; cc++) acc2[nt][cc] = 0.f;

#pragma unroll
    for (int ksi = 0; ksi < 8; ksi++) {
        int col = ksi * 8 + t;
        unsigned a[4];
        a[0] = __float_as_uint(sh1[row0 * MS + col]);
        a[1] = __float_as_uint(sh1[(row0 + 8) * MS + col]);
        a[2] = __float_as_uint(sh1[row0 * MS + col + 4]);
        a[3] = __float_as_uint(sh1[(row0 + 8) * MS + col + 4]);
        const float4* wr = (const float4*)&sW2[(ksi * 32 + lane) * 20];
        float4 w0 = wr[0], w1 = wr[1], w2 = wr[2], w3 = wr[3];
        mma_tf32(acc2[0], a, __float_as_uint(w0.x), __float_as_uint(w0.y));
        mma_tf32(acc2[1], a, __float_as_uint(w0.z), __float_as_uint(w0.w));
        mma_tf32(acc2[2], a, __float_as_uint(w1.x), __float_as_uint(w1.y));
        mma_tf32(acc2[3], a, __float_as_uint(w1.z), __float_as_uint(w1.w));
        mma_tf32(acc2[4], a, __float_as_uint(w2.x), __float_as_uint(w2.y));
        mma_tf32(acc2[5], a, __float_as_uint(w2.z), __float_as_uint(w2.w));
        mma_tf32(acc2[6], a, __float_as_uint(w3.x), __float_as_uint(w3.y));
        mma_tf32(acc2[7], a, __float_as_uint(w3.z), __float_as_uint(w3.w));
    }

    // Epilogue
    float p0[8], p1[8];
#pragma unroll
    for (int h = 0; h < 8; h++) { p0[h] = 0.f; p1[h] = 0.f; }

#pragma unroll
    for (int nt = 0; nt < 8; nt++) {
        int col0 = nt * 8 + 2 * t, col1 = col0 + 1;
        float b0 = sb2[col0], b1v = sb2[col1];
        float h00 = ftanh(acc2[nt][0] + b0);
        float h01 = ftanh(acc2[nt][1] + b1v);
        float h10 = ftanh(acc2[nt][2] + b0);
        float h11 = ftanh(acc2[nt][3] + b1v);
        float4 wa0 = *(float4*)&sW3[col0 * 8];
        float4 wa1 = *(float4*)&sW3[col0 * 8 + 4];
        float4 wb0 = *(float4*)&sW3[col1 * 8];
        float4 wb1 = *(float4*)&sW3[col1 * 8 + 4];
        p0[0] += h00 * wa0.x + h01 * wb0.x;  p0[1] += h00 * wa0.y + h01 * wb0.y;
        p0[2] += h00 * wa0.z + h01 * wb0.z;  p0[3] += h00 * wa0.w + h01 * wb0.w;
        p0[4] += h00 * wa1.x + h01 * wb1.x;  p0[5] += h00 * wa1.y + h01 * wb1.y;
        p0[6] += h00 * wa1.z + h01 * wb1.z;  p0[7] += h00 * wa1.w + h01 * wb1.w;
        p1[0] += h10 * wa0.x + h11 * wb0.x;  p1[1] += h10 * wa0.y + h11 * wb0.y;
        p1[2] += h10 * wa0.z + h11 * wb0.z;  p1[3] += h10 * wa0.w + h11 * wb0.w;
        p1[4] += h10 * wa1.x + h11 * wb1.x;  p1[5] += h10 * wa1.y + h11 * wb1.y;
        p1[6] += h10 * wa1.z + h11 * wb1.z;  p1[7] += h10 * wa1.w + h11 * wb1.w;
    }
#pragma unroll
    for (int h = 0; h < 8; h++) {
        p0[h] += __shfl_xor_sync(0xffffffffu, p0[h], 1);
        p0[h] += __shfl_xor_sync(0xffffffffu, p0[h], 2);
        p1[h] += __shfl_xor_sync(0xffffffffu, p1[h], 1);
        p1[h] += __shfl_xor_sync(0xffffffffu, p1[h], 2);
    }
    int sg0 = s0 + row0, sg1 = sg0 + 8;
#pragma unroll
    for (int hh2 = 0; hh2 < 2; hh2++) {
        int h = 2 * t + hh2;
        float* P0 = &g_P[(size_t)h * (N_NODES * N_NODES) + (size_t)r * 512 + sg0];
        float* P1 = &g_P[(size_t)h * (N_NODES * N_NODES) + (size_t)r * 512 + sg1];
        *P0 += p0[h] + sb3[h];
        *P1 += p1[h] + sb3[h];
    }
}

// ================= Kernel 5: fused softmax + aggregation + residual =================
#define PS 516
#define AGS 68
#define SMEM_AGG ((16 * PS + 64 * AGS) * 4)

__device__ __forceinline__ int head_col(int h, int c) {
    if (c < 16) return h * 16 + c;
    if (c < 40) return 128 + h * 24 + (c - 16);
    return 320 + h * 20 + (c - 40);
}

__global__ void __launch_bounds__(256, 3) k_agg(
    const float* __restrict__ node_feat, float* __restrict__ out)
{
    extern __shared__ float smA[];
    float* sP = smA;              // [16][PS]
    float* sV = smA + 16 * PS;    // [64][AGS]

    int tid = threadIdx.x;
    int h = blockIdx.x >> 5, rt = blockIdx.x & 31;
    int r0 = rt * 16;

    const float* Pb = g_P + (size_t)h * (N_NODES * N_NODES);
    for (int i = tid; i < 2048; i += 256) {
        int r_l = i >> 7, s4 = i & 127;
        float4 v = *(const float4*)&Pb[(size_t)(r0 + r_l) * 512 + s4 * 4];
        *(float4*)&sP[r_l * PS + s4 * 4] = v;
    }
    __syncthreads();

    int w = tid >> 5, lane = tid & 31;

#pragma unroll
    for (int rr = 0; rr < 2; rr++) {
        float* row = &sP[(w * 2 + rr) * PS];
        float v[16];
        float mx = -1e30f;
#pragma unroll
        for (int k = 0; k < 16; k++) { v[k] = row[lane + 32 * k]; mx = fmaxf(mx, v[k]); }
#pragma unroll
        for (int o = 16; o; o >>= 1) mx = fmaxf(mx, __shfl_xor_sync(0xffffffffu, mx, o));
        float sum = 0.f;
#pragma unroll
        for (int k = 0; k < 16; k++) { v[k] = __expf(v[k] - mx); sum += v[k]; }
#pragma unroll
        for (int o = 16; o; o >>= 1) sum += __shfl_xor_sync(0xffffffffu, sum, o);
        float rinv = __fdividef(1.0f, sum);
#pragma unroll
        for (int k = 0; k < 16; k++) row[lane + 32 * k] = f2tf32f(v[k] * rinv);
    }

    int g = lane >> 2, t = lane & 3;
    float acc[4] = {0.f, 0.f, 0.f, 0.f};

    for (int kc = 0; kc < 8; kc++) {
        __syncthreads();
        for (int i = tid; i < 4096; i += 256) {
            int c_l = i >> 6, s_l = i & 63;
            float val = 0.f;
            if (c_l < 60) val = g_vmT[(size_t)head_col(h, c_l) * 512 + kc * 64 + s_l];
            sV[c_l * AGS + s_l] = f2tf32f(val);
        }
        __syncthreads();
#pragma unroll
        for (int ksi = 0; ksi < 8; ksi++) {
            int colg = kc * 64 + ksi * 8 + t;
            unsigned a[4];
            a[0] = __float_as_uint(sP[g * PS + colg]);
            a[1] = __float_as_uint(sP[(g + 8) * PS + colg]);
            a[2] = __float_as_uint(sP[g * PS + colg + 4]);
            a[3] = __float_as_uint(sP[(g + 8) * PS + colg + 4]);
            int col = ksi * 8 + t;
            unsigned b0 = __float_as_uint(sV[(w * 8 + g) * AGS + col]);
            unsigned b1 = __float_as_uint(sV[(w * 8 + g) * AGS + col + 4]);
            mma_tf32(acc, a, b0, b1);
        }
    }

    int c0 = w * 8 + 2 * t;
    if (c0 < 60) {
        int cg = head_col(h, c0);
        int rg0 = r0 + g, rg1 = rg0 + 8;
        float2 nf0 = *(const float2*)&node_feat[(size_t)rg0 * 480 + cg];
        float2 nf1 = *(const float2*)&node_feat[(size_t)rg1 * 480 + cg];
        *(float2*)&out[(size_t)rg0 * 480 + cg] = make_float2(nf0.x + acc[0], nf0.y + acc[1]);
        *(float2*)&out[(size_t)rg1 * 480 + cg] = make_float2(nf1.x + acc[2], nf1.y + acc[3]);
    }
}

// ================= launch =================
extern "C" void kernel_launch(void* const* d_in, const int* in_sizes, int n_in,
                              void* d_out, int out_size)
{
    const float* node_feat = (const float*)d_in[0];
    const float* edge_attr = (const float*)d_in[1];
    const float* edge_sh   = (const float*)d_in[2];
    const float* Wq0 = (const float*)d_in[3];
    const float* Wq1 = (const float*)d_in[4];
    const float* Wq2 = (const float*)d_in[5];
    const float* Wk0 = (const float*)d_in[6];
    const float* Wk1 = (const float*)d_in[7];
    const float* Wk2 = (const float*)d_in[8];
    const float* Wv0 = (const float*)d_in[9];
    const float* Wv1 = (const float*)d_in[10];
    const float* Wv2 = (const float*)d_in[11];
    const float* mW1 = (const float*)d_in[12];
    const float* mb1 = (const float*)d_in[13];
    const float* mW2 = (const float*)d_in[14];
    const float* mb2 = (const float*)d_in[15];
    const float* mW3 = (const float*)d_in[16];
    const float* mb3 = (const float*)d_in[17];
    float* out = (float*)d_out;

    cudaFuncSetAttribute(k_mlp, cudaFuncAttributeMaxDynamicSharedMemorySize, SMEM_MLP);
    cudaFuncSetAttribute(k_agg, cudaFuncAttributeMaxDynamicSharedMemorySize, SMEM_AGG);

    k_prep_w<<<1, 256>>>(mW1, mW2);
    k_node<<<dim3(128, 8), 256>>>(node_feat, Wq0, Wq1, Wq2, Wk0, Wk1, Wk2, Wv0, Wv1, Wv2, mW1);
    k_prep_ab<<<512, 256>>>();
    k_XB<<<2048, 256>>>(edge_sh, mb1);
    k_logit<<<512, 256>>>();
    k_mlp<<<2048, 256, SMEM_MLP>>>(edge_attr, edge_sh, mb2, mW3, mb3);
    k_agg<<<256, 256, SMEM_AGG>>>(node_feat, out);
}

// round 16
// speedup vs baseline: 1.0905x; 1.0905x over previous
#include <cuda_runtime.h>
#include <cuda_bf16.h>
#include <cstddef>

#define N_NODES 512
#define H 8

// ---------------- device scratch ----------------
__device__ __align__(16) float g_qh[N_NODES * H * 60];
__device__ __align__(16) float g_kh[N_NODES * H * 60];
__device__ __align__(16) float g_A[N_NODES * 9 * 64];
__device__ __align__(16) float g_B[N_NODES * 9 * 64];
__device__ __align__(16) float g_vmT[480 * N_NODES];
__device__ __align__(16) float g_X[(size_t)N_NODES * N_NODES * 64];   // b1 + sh*B[s]
__device__ __align__(16) float g_P[(size_t)H * N_NODES * N_NODES];    // planes [h][r][s]
// fragment-order precomputes
__device__ __align__(16) float g_W2f[4096];            // W2 fragments (8 ksi)
__device__ __align__(16) float g_W1f[2048];            // W1a fragments (4 ksi)
__device__ __align__(16) float g_Af[N_NODES * 1024];   // A[r] fragments (2 ksi)
__device__ __align__(16) float g_Bsf[N_NODES * 1024];  // B[s] fragments (2 ksi)

#define CG1 0.5773502691896258f
#define CG2 0.4472135954999579f
#define ATTN_NORM 0.1889822365046136f
#define RS128 0.08838834764831845f
#define RS64  0.125f
#define RS32  0.17677669529663687f

__device__ __forceinline__ float ftanh(float x) {
    return 1.0f - __fdividef(2.0f, __expf(2.0f * x) + 1.0f);
}

__device__ __forceinline__ float f2tf32f(float x) {
    unsigned u;
    asm("cvt.rna.tf32.f32 %0, %1;" : "=r"(u) : "f"(x));
    return __uint_as_float(u);
}

__device__ __forceinline__ unsigned f2tf32u(float x) {
    unsigned u;
    asm("cvt.rna.tf32.f32 %0, %1;" : "=r"(u) : "f"(x));
    return u;
}

__device__ __forceinline__ void mma_tf32(float* c, const unsigned* a, unsigned b0, unsigned b1) {
    asm volatile(
        "mma.sync.aligned.m16n8k8.row.col.f32.tf32.tf32.f32 "
        "{%0,%1,%2,%3}, {%4,%5,%6,%7}, {%8,%9}, {%0,%1,%2,%3};\n"
        : "+f"(c[0]), "+f"(c[1]), "+f"(c[2]), "+f"(c[3])
        : "r"(a[0]), "r"(a[1]), "r"(a[2]), "r"(a[3]), "r"(b0), "r"(b1));
}

// ================= Kernel 0a: weight fragment precompute (once) =================
__global__ void __launch_bounds__(256) k_prep_w(
    const float* __restrict__ mW1, const float* __restrict__ mW2)
{
    int tid = threadIdx.x;
    for (int i = tid; i < 4096; i += 256) {
        int ksi = i >> 9, rem = i & 511;
        int lane_ = rem >> 4, j = rem & 15;
        int t_ = lane_ & 3, g_ = lane_ >> 2;
        int nt = j >> 1, p = j & 1;
        int k = ksi * 8 + t_ + 4 * p;
        int n = nt * 8 + g_;
        g_W2f[(ksi * 32 + lane_) * 16 + j] = f2tf32f(mW2[k * 64 + n]);
    }
    for (int i = tid; i < 2048; i += 256) {
        int ksi = i >> 9, rem = i & 511;
        int lane_ = rem >> 4, j = rem & 15;
        int t_ = lane_ & 3, g_ = lane_ >> 2;
        int nt = j >> 1, p = j & 1;
        int k = ksi * 8 + t_ + 4 * p;   // < 32
        int n = nt * 8 + g_;
        g_W1f[(ksi * 32 + lane_) * 16 + j] = f2tf32f(mW1[k * 64 + n]);
    }
}

// ================= Kernel 0b: per-node A/B fragment precompute =================
__global__ void __launch_bounds__(256) k_prep_ab()
{
    int n = blockIdx.x;
    int tid = threadIdx.x;
    for (int i = tid; i < 1024; i += 256) {
        int ksi = i >> 9, rem = i & 511;
        int lane_ = rem >> 4, j = rem & 15;
        int t_ = lane_ & 3, g_ = lane_ >> 2;
        int nt = j >> 1, p = j & 1;
        int k = ksi * 8 + t_ + 4 * p;
        int c = nt * 8 + g_;
        float va = (k < 9) ? g_A[(size_t)n * 576 + k * 64 + c] : 0.f;
        g_Af[(size_t)n * 1024 + (ksi * 32 + lane_) * 16 + j] = f2tf32f(va);
        float vb = (k < 9) ? g_B[(size_t)n * 576 + k * 64 + c] : 0.f;
        g_Bsf[(size_t)n * 1024 + (ksi * 32 + lane_) * 16 + j] = f2tf32f(vb);
    }
}

// ================= Kernel 1: per-node precompute =================
__global__ void __launch_bounds__(256) k_node(
    const float* __restrict__ node_feat,
    const float* __restrict__ Wq0, const float* __restrict__ Wq1, const float* __restrict__ Wq2,
    const float* __restrict__ Wk0, const float* __restrict__ Wk1, const float* __restrict__ Wk2,
    const float* __restrict__ Wv0, const float* __restrict__ Wv1, const float* __restrict__ Wv2,
    const float* __restrict__ mW1)
{
    __shared__ float snf[4 * 480];
    int tid = threadIdx.x;
    int n0 = blockIdx.x * 4;

    for (int i = tid; i < 480; i += 256) {
        int nn = i / 120, c4 = i % 120;
        float4 v = *(const float4*)&node_feat[(size_t)(n0 + nn) * 480 + c4 * 4];
        snf[nn * 480 + c4 * 4 + 0] = v.x;
        snf[nn * 480 + c4 * 4 + 1] = v.y;
        snf[nn * 480 + c4 * 4 + 2] = v.z;
        snf[nn * 480 + c4 * 4 + 3] = v.w;
    }
    __syncthreads();

    int gend = 162 * (blockIdx.y + 1);
    for (int g = tid + 162 * blockIdx.y; g < gend; g += 256) {
        int kind, l, m, o, mul, off, mp = 0, stride;
        const float* Wp;
        if (g < 360) {
            int mat = g / 120, gg = g % 120;
            if (gg < 32)      { l = 0; m = 0;              o = gg * 4; }
            else if (gg < 80) { int t = gg - 32; l = 1; o = (t / 3) * 4; m = t % 3; }
            else              { int t = gg - 80; l = 2; o = (t / 5) * 4; m = t % 5; }
            mul = (l == 0) ? 128 : (l == 1) ? 64 : 32;
            off = (l == 0) ? 0 : (l == 1) ? 128 : 320;
            stride = mul;
            if (mat == 0)      Wp = (l == 0) ? Wq0 : (l == 1) ? Wq1 : Wq2;
            else if (mat == 1) Wp = (l == 0) ? Wk0 : (l == 1) ? Wk1 : Wk2;
            else               Wp = (l == 0) ? Wv0 : (l == 1) ? Wv1 : Wv2;
            kind = mat;
        } else {
            int t = g - 360;
            int ab = t / 144, u = t % 144;
            mp = u / 16; o = (u % 16) * 4;
            l = (mp == 0) ? 0 : (mp < 4) ? 1 : 2;
            m = (mp == 0) ? 0 : (mp < 4) ? (mp - 1) : (mp - 4);
            mul = (l == 0) ? 128 : (l == 1) ? 64 : 32;
            off = (l == 0) ? 0 : (l == 1) ? 128 : 320;
            int row = ((l == 0) ? 32 : (l == 1) ? 160 : 224) + ab * 224;
            Wp = mW1 + (size_t)row * 64;
            stride = 64;
            kind = 3 + ab;
        }
        int d = 2 * l + 1;

        float4 a0 = make_float4(0.f,0.f,0.f,0.f), a1 = a0, a2 = a0, a3 = a0;
#pragma unroll 4
        for (int i = 0; i < mul; i++) {
            float4 wv = __ldg((const float4*)&Wp[(size_t)i * stride + o]);
            int col = off + i * d + m;
            float x0 = snf[col], x1 = snf[480 + col], x2 = snf[960 + col], x3 = snf[1440 + col];
            a0.x += x0 * wv.x; a0.y += x0 * wv.y; a0.z += x0 * wv.z; a0.w += x0 * wv.w;
            a1.x += x1 * wv.x; a1.y += x1 * wv.y; a1.z += x1 * wv.z; a1.w += x1 * wv.w;
            a2.x += x2 * wv.x; a2.y += x2 * wv.y; a2.z += x2 * wv.z; a2.w += x2 * wv.w;
            a3.x += x3 * wv.x; a3.y += x3 * wv.y; a3.z += x3 * wv.z; a3.w += x3 * wv.w;
        }

        float rs = (l == 0) ? RS128 : (l == 1) ? RS64 : RS32;
        float cg = (l == 0) ? 1.f   : (l == 1) ? CG1  : CG2;
        float accs[4][4] = {{a0.x,a0.y,a0.z,a0.w},{a1.x,a1.y,a1.z,a1.w},
                            {a2.x,a2.y,a2.z,a2.w},{a3.x,a3.y,a3.z,a3.w}};
#pragma unroll
        for (int nn = 0; nn < 4; nn++) {
            int n = n0 + nn;
#pragma unroll
            for (int oo = 0; oo < 4; oo++) {
                int o_ = o + oo;
                float a = accs[nn][oo];
                if (kind <= 1) {
                    int am = mul >> 3;
                    int hh = o_ / am, oi = o_ % am;
                    int j = (l == 0) ? oi : (l == 1) ? (16 + oi * 3 + m) : (40 + oi * 5 + m);
                    size_t idx = ((size_t)n * H + hh) * 60 + j;
                    if (kind == 0) g_qh[idx] = a * rs * cg * ATTN_NORM;
                    else           g_kh[idx] = a * rs;
                } else if (kind == 2) {
                    int w = (l == 0) ? o_ : (l == 1) ? (128 + o_ * 3 + m) : (320 + o_ * 5 + m);
                    g_vmT[(size_t)w * N_NODES + n] = a * rs;
                } else {
                    float* dst = (kind == 3) ? g_A : g_B;
                    dst[((size_t)n * 9 + mp) * 64 + o_] = a * cg;
                }
            }
        }
    }
}

// ================= Kernel 2: X = b1 + sh*B[s]  (small tf32 GEMM, s-grouped) =================
__global__ void __launch_bounds__(256) k_XB(
    const float* __restrict__ edge_sh, const float* __restrict__ mb1)
{
    __shared__ float shs[128 * 9];     // sh[r][m] tf32 bits
    __shared__ float sBf[2 * 32 * 20]; // B[s] fragments, stride 20
    __shared__ float sb1[64];

    int tid = threadIdx.x;
    int s = blockIdx.x >> 2;
    int r0 = (blockIdx.x & 3) * 128;

    for (int i = tid; i < 1152; i += 256) {
        int r_l = i / 9, m = i % 9;
        shs[r_l * 9 + m] = f2tf32f(__ldg(&edge_sh[((size_t)(r0 + r_l) * 512 + s) * 9 + m]));
    }
    for (int i = tid; i < 256; i += 256) {
        int row = i >> 2, q = i & 3;
        *(float4*)&sBf[row * 20 + q * 4] = ((const float4*)(g_Bsf + (size_t)s * 1024))[i];
    }
    if (tid < 64) sb1[tid] = mb1[tid];
    __syncthreads();

    int w = tid >> 5, lane = tid & 31;
    int g = lane >> 2, t = lane & 3;
    int row0 = w * 16 + g;

    float acc[8][4];
#pragma unroll
    for (int nt = 0; nt < 8; nt++)
#pragma unroll
        for (int cc = 0; cc < 4; cc++) acc[nt][cc] = 0.f;

#pragma unroll
    for (int ksi = 0; ksi < 2; ksi++) {
        int col = ksi * 8 + t;
        unsigned a[4];
        a[0] = (col < 9)     ? __float_as_uint(shs[row0 * 9 + col])           : 0u;
        a[1] = (col < 9)     ? __float_as_uint(shs[(row0 + 8) * 9 + col])     : 0u;
        a[2] = (col + 4 < 9) ? __float_as_uint(shs[row0 * 9 + col + 4])       : 0u;
        a[3] = (col + 4 < 9) ? __float_as_uint(shs[(row0 + 8) * 9 + col + 4]) : 0u;
        const float4* wr = (const float4*)&sBf[(ksi * 32 + lane) * 20];
        float4 w0 = wr[0], w1 = wr[1], w2 = wr[2], w3 = wr[3];
        mma_tf32(acc[0], a, __float_as_uint(w0.x), __float_as_uint(w0.y));
        mma_tf32(acc[1], a, __float_as_uint(w0.z), __float_as_uint(w0.w));
        mma_tf32(acc[2], a, __float_as_uint(w1.x), __float_as_uint(w1.y));
        mma_tf32(acc[3], a, __float_as_uint(w1.z), __float_as_uint(w1.w));
        mma_tf32(acc[4], a, __float_as_uint(w2.x), __float_as_uint(w2.y));
        mma_tf32(acc[5], a, __float_as_uint(w2.z), __float_as_uint(w2.w));
        mma_tf32(acc[6], a, __float_as_uint(w3.x), __float_as_uint(w3.y));
        mma_tf32(acc[7], a, __float_as_uint(w3.z), __float_as_uint(w3.w));
    }

#pragma unroll
    for (int nt = 0; nt < 8; nt++) {
        int col0 = nt * 8 + 2 * t;
        float b0 = sb1[col0], b1v = sb1[col0 + 1];
        *(float2*)&g_X[((size_t)(r0 + row0) * 512 + s) * 64 + col0] =
            make_float2(acc[nt][0] + b0, acc[nt][1] + b1v);
        *(float2*)&g_X[((size_t)(r0 + row0 + 8) * 512 + s) * 64 + col0] =
            make_float2(acc[nt][2] + b0, acc[nt][3] + b1v);
    }
}

// ================= Kernel 3: logits tf32 tensor GEMM, natural [n][k] staging =================
#define LQS 68
__global__ void __launch_bounds__(256) k_logit()
{
    __shared__ float sQ[64 * LQS];   // [r][k], k padded to 64
    __shared__ float sK[64 * LQS];   // [s][k], k padded to 64
    int tid = threadIdx.x;
    int hh = blockIdx.x >> 6, tile = blockIdx.x & 63;
    int r0 = (tile >> 3) * 64, s0 = (tile & 7) * 64;

    for (int i = tid; i < 960; i += 256) {
        int nl = i / 15, k4 = i % 15;
        float4 vq = *(const float4*)&g_qh[((size_t)(r0 + nl) * H + hh) * 60 + k4 * 4];
        float4 vk = *(const float4*)&g_kh[((size_t)(s0 + nl) * H + hh) * 60 + k4 * 4];
        float* qd = &sQ[nl * LQS + k4 * 4];
        float* kd = &sK[nl * LQS + k4 * 4];
        qd[0] = f2tf32f(vq.x); qd[1] = f2tf32f(vq.y); qd[2] = f2tf32f(vq.z); qd[3] = f2tf32f(vq.w);
        kd[0] = f2tf32f(vk.x); kd[1] = f2tf32f(vk.y); kd[2] = f2tf32f(vk.z); kd[3] = f2tf32f(vk.w);
    }
    for (int i = tid; i < 256; i += 256) {
        int nl = i >> 2, kk = 60 + (i & 3);
        sQ[nl * LQS + kk] = 0.f;
        sK[nl * LQS + kk] = 0.f;
    }
    __syncthreads();

    int w = tid >> 5, lane = tid & 31;
    int g = lane >> 2, t = lane & 3;
    int mt = w & 3, nq = w >> 2;
    int row0 = mt * 16 + g;

    float acc[4][4];
#pragma unroll
    for (int nt = 0; nt < 4; nt++)
#pragma unroll
        for (int cc = 0; cc < 4; cc++) acc[nt][cc] = 0.f;

#pragma unroll
    for (int ksi = 0; ksi < 8; ksi++) {
        int col = ksi * 8 + t;
        unsigned a[4];
        a[0] = __float_as_uint(sQ[row0 * LQS + col]);
        a[1] = __float_as_uint(sQ[(row0 + 8) * LQS + col]);
        a[2] = __float_as_uint(sQ[row0 * LQS + col + 4]);
        a[3] = __float_as_uint(sQ[(row0 + 8) * LQS + col + 4]);
#pragma unroll
        for (int nt = 0; nt < 4; nt++) {
            int n = nq * 32 + nt * 8 + g;
            unsigned b0 = __float_as_uint(sK[n * LQS + col]);
            unsigned b1 = __float_as_uint(sK[n * LQS + col + 4]);
            mma_tf32(acc[nt], a, b0, b1);
        }
    }

    float* base = g_P + (size_t)hh * (N_NODES * N_NODES);
#pragma unroll
    for (int nt = 0; nt < 4; nt++) {
        int c0 = s0 + nq * 32 + nt * 8 + 2 * t;
        *(float2*)&base[(size_t)(r0 + row0) * 512 + c0] = make_float2(acc[nt][0], acc[nt][1]);
        *(float2*)&base[(size_t)(r0 + row0 + 8) * 512 + c0] = make_float2(acc[nt][2], acc[nt][3]);
    }
}

// ================= Kernel 4: ea GEMM + sh*A GEMM + X add + tanh + GEMM2 + epilogue -> P ====
#define MS 68
#define SMEM_MLP (17480 * 4)

__global__ void __launch_bounds__(256, 3) k_mlp(
    const float* __restrict__ edge_attr, const float* __restrict__ edge_sh,
    const float* __restrict__ mb2,
    const float* __restrict__ mW3, const float* __restrict__ mb3)
{
    extern __shared__ float sm[];
    float* sh1 = sm;                    // [128][MS] : first ea (tf32, cols 0..31), then h1
    float* sW2 = sh1 + 128 * MS;        // [5120] W2 fragments, stride 20
    float* sAf = sW2 + 5120;            // [1024] A[r] fragments, compact stride 16
    float* sW1f = sAf + 1024;           // [2048] W1a fragments, compact stride 16
    float* sW3 = sW1f + 2048;           // [64][8]
    float* sb2 = sW3 + 512;
    float* sb3 = sb2 + 64;

    int tid = threadIdx.x;
    int r = blockIdx.x >> 2;
    int s0 = (blockIdx.x & 3) * 128;

    for (int i = tid; i < 1024; i += 256) {
        int row = i >> 2, q = i & 3;
        *(float4*)&sW2[row * 20 + q * 4] = ((const float4*)g_W2f)[i];
    }
    for (int i = tid; i < 512; i += 256)
        ((float4*)sW1f)[i] = ((const float4*)g_W1f)[i];
    for (int i = tid; i < 256; i += 256)
        ((float4*)sAf)[i] = ((const float4*)(g_Af + (size_t)r * 1024))[i];
    for (int i = tid; i < 512; i += 256) sW3[i] = mW3[i];
    if (tid < 64) sb2[tid] = mb2[tid];
    if (tid < 8)  sb3[tid] = mb3[tid];

    for (int i = tid; i < 1024; i += 256) {
        int s_l = i >> 3, k4 = i & 7;
        float4 v = __ldg((const float4*)&edge_attr[((size_t)r * 512 + s0 + s_l) * 32 + k4 * 4]);
        float4 o;
        o.x = f2tf32f(v.x); o.y = f2tf32f(v.y); o.z = f2tf32f(v.z); o.w = f2tf32f(v.w);
        *(float4*)&sh1[s_l * MS + k4 * 4] = o;
    }
    __syncthreads();

    int w = tid >> 5, lane = tid & 31;
    int g = lane >> 2, t = lane & 3;
    int row0 = w * 16 + g;

    float accA[8][4];
#pragma unroll
    for (int nt = 0; nt < 8; nt++)
#pragma unroll
        for (int cc = 0; cc < 4; cc++) accA[nt][cc] = 0.f;

    // GEMM-ea: ea[128,32] @ W1a[32,64]
#pragma unroll
    for (int ksi = 0; ksi < 4; ksi++) {
        int col = ksi * 8 + t;
        unsigned a[4];
        a[0] = __float_as_uint(sh1[row0 * MS + col]);
        a[1] = __float_as_uint(sh1[(row0 + 8) * MS + col]);
        a[2] = __float_as_uint(sh1[row0 * MS + col + 4]);
        a[3] = __float_as_uint(sh1[(row0 + 8) * MS + col + 4]);
        const float4* wr = (const float4*)&sW1f[(ksi * 32 + lane) * 16];
        float4 w0 = wr[0], w1 = wr[1], w2 = wr[2], w3 = wr[3];
        mma_tf32(accA[0], a, __float_as_uint(w0.x), __float_as_uint(w0.y));
        mma_tf32(accA[1], a, __float_as_uint(w0.z), __float_as_uint(w0.w));
        mma_tf32(accA[2], a, __float_as_uint(w1.x), __float_as_uint(w1.y));
        mma_tf32(accA[3], a, __float_as_uint(w1.z), __float_as_uint(w1.w));
        mma_tf32(accA[4], a, __float_as_uint(w2.x), __float_as_uint(w2.y));
        mma_tf32(accA[5], a, __float_as_uint(w2.z), __float_as_uint(w2.w));
        mma_tf32(accA[6], a, __float_as_uint(w3.x), __float_as_uint(w3.y));
        mma_tf32(accA[7], a, __float_as_uint(w3.z), __float_as_uint(w3.w));
    }

    // GEMM-A: sh[128,9(pad16)] @ A[r][9,64]; a-operands loaded directly from gmem
    {
        const float* shr0 = edge_sh + ((size_t)r * 512 + s0 + row0) * 9;
        const float* shr1 = shr0 + 8 * 9;
#pragma unroll
        for (int ksi = 0; ksi < 2; ksi++) {
            int col = ksi * 8 + t;
            unsigned a[4];
            a[0] = (col < 9)     ? f2tf32u(__ldg(shr0 + col))     : 0u;
            a[1] = (col < 9)     ? f2tf32u(__ldg(shr1 + col))     : 0u;
            a[2] = (col + 4 < 9) ? f2tf32u(__ldg(shr0 + col + 4)) : 0u;
            a[3] = (col + 4 < 9) ? f2tf32u(__ldg(shr1 + col + 4)) : 0u;
            const float4* wr = (const float4*)&sAf[(ksi * 32 + lane) * 16];
            float4 w0 = wr[0], w1 = wr[1], w2 = wr[2], w3 = wr[3];
            mma_tf32(accA[0], a, __float_as_uint(w0.x), __float_as_uint(w0.y));
            mma_tf32(accA[1], a, __float_as_uint(w0.z), __float_as_uint(w0.w));
            mma_tf32(accA[2], a, __float_as_uint(w1.x), __float_as_uint(w1.y));
            mma_tf32(accA[3], a, __float_as_uint(w1.z), __float_as_uint(w1.w));
            mma_tf32(accA[4], a, __float_as_uint(w2.x), __float_as_uint(w2.y));
            mma_tf32(accA[5], a, __float_as_uint(w2.z), __float_as_uint(w2.w));
            mma_tf32(accA[6], a, __float_as_uint(w3.x), __float_as_uint(w3.y));
            mma_tf32(accA[7], a, __float_as_uint(w3.z), __float_as_uint(w3.w));
        }
    }

    // X add + tanh + store h1 fragments
    {
        const float* Xr0 = &g_X[((size_t)r * 512 + s0 + row0) * 64];
        const float* Xr1 = Xr0 + 8 * 64;
#pragma unroll
        for (int nt = 0; nt < 8; nt++) {
            int c0 = nt * 8 + 2 * t;
            float2 x0 = *(const float2*)&Xr0[c0];
            float2 x1 = *(const float2*)&Xr1[c0];
            float h00 = f2tf32f(ftanh(x0.x + accA[nt][0]));
            float h01 = f2tf32f(ftanh(x0.y + accA[nt][1]));
            float h10 = f2tf32f(ftanh(x1.x + accA[nt][2]));
            float h11 = f2tf32f(ftanh(x1.y + accA[nt][3]));
            *(float2*)&sh1[row0 * MS + c0] = make_float2(h00, h01);
            *(float2*)&sh1[(row0 + 8) * MS + c0] = make_float2(h10, h11);
        }
    }
    __syncthreads();

    // GEMM2
    float acc2[8][4];
#pragma unroll
    for (int nt = 0; nt < 8; nt++)
#pragma unroll
        for (int cc = 0; cc < 4; cc++) acc2[nt][cc] = 0.f;

#pragma unroll
    for (int ksi = 0; ksi < 8; ksi++) {
        int col = ksi * 8 + t;
        unsigned a[4];
        a[0] = __float_as_uint(sh1[row0 * MS + col]);
        a[1] = __float_as_uint(sh1[(row0 + 8) * MS + col]);
        a[2] = __float_as_uint(sh1[row0 * MS + col + 4]);
        a[3] = __float_as_uint(sh1[(row0 + 8) * MS + col + 4]);
        const float4* wr = (const float4*)&sW2[(ksi * 32 + lane) * 20];
        float4 w0 = wr[0], w1 = wr[1], w2 = wr[2], w3 = wr[3];
        mma_tf32(acc2[0], a, __float_as_uint(w0.x), __float_as_uint(w0.y));
        mma_tf32(acc2[1], a, __float_as_uint(w0.z), __float_as_uint(w0.w));
        mma_tf32(acc2[2], a, __float_as_uint(w1.x), __float_as_uint(w1.y));
        mma_tf32(acc2[3], a, __float_as_uint(w1.z), __float_as_uint(w1.w));
        mma_tf32(acc2[4], a, __float_as_uint(w2.x), __float_as_uint(w2.y));
        mma_tf32(acc2[5], a, __float_as_uint(w2.z), __float_as_uint(w2.w));
        mma_tf32(acc2[6], a, __float_as_uint(w3.x), __float_as_uint(w3.y));
        mma_tf32(acc2[7], a, __float_as_uint(w3.z), __float_as_uint(w3.w));
    }

    // Epilogue
    float p0[8], p1[8];
#pragma unroll
    for (int h = 0; h < 8; h++) { p0[h] = 0.f; p1[h] = 0.f; }

#pragma unroll
    for (int nt = 0; nt < 8; nt++) {
        int col0 = nt * 8 + 2 * t, col1 = col0 + 1;
        float b0 = sb2[col0], b1v = sb2[col1];
        float h00 = ftanh(acc2[nt][0] + b0);
        float h01 = ftanh(acc2[nt][1] + b1v);
        float h10 = ftanh(acc2[nt][2] + b0);
        float h11 = ftanh(acc2[nt][3] + b1v);
        float4 wa0 = *(float4*)&sW3[col0 * 8];
        float4 wa1 = *(float4*)&sW3[col0 * 8 + 4];
        float4 wb0 = *(float4*)&sW3[col1 * 8];
        float4 wb1 = *(float4*)&sW3[col1 * 8 + 4];
        p0[0] += h00 * wa0.x + h01 * wb0.x;  p0[1] += h00 * wa0.y + h01 * wb0.y;
        p0[2] += h00 * wa0.z + h01 * wb0.z;  p0[3] += h00 * wa0.w + h01 * wb0.w;
        p0[4] += h00 * wa1.x + h01 * wb1.x;  p0[5] += h00 * wa1.y + h01 * wb1.y;
        p0[6] += h00 * wa1.z + h01 * wb1.z;  p0[7] += h00 * wa1.w + h01 * wb1.w;
        p1[0] += h10 * wa0.x + h11 * wb0.x;  p1[1] += h10 * wa0.y + h11 * wb0.y;
        p1[2] += h10 * wa0.z + h11 * wb0.z;  p1[3] += h10 * wa0.w + h11 * wb0.w;
        p1[4] += h10 * wa1.x + h11 * wb1.x;  p1[5] += h10 * wa1.y + h11 * wb1.y;
        p1[6] += h10 * wa1.z + h11 * wb1.z;  p1[7] += h10 * wa1.w + h11 * wb1.w;
    }
#pragma unroll
    for (int h = 0; h < 8; h++) {
        p0[h] += __shfl_xor_sync(0xffffffffu, p0[h], 1);
        p0[h] += __shfl_xor_sync(0xffffffffu, p0[h], 2);
        p1[h] += __shfl_xor_sync(0xffffffffu, p1[h], 1);
        p1[h] += __shfl_xor_sync(0xffffffffu, p1[h], 2);
    }
    int sg0 = s0 + row0, sg1 = sg0 + 8;
#pragma unroll
    for (int hh2 = 0; hh2 < 2; hh2++) {
        int h = 2 * t + hh2;
        float* P0 = &g_P[(size_t)h * (N_NODES * N_NODES) + (size_t)r * 512 + sg0];
        float* P1 = &g_P[(size_t)h * (N_NODES * N_NODES) + (size_t)r * 512 + sg1];
        *P0 += p0[h] + sb3[h];
        *P1 += p1[h] + sb3[h];
    }
}

// ================= Kernel 5: fused softmax + aggregation + residual =================
#define PS 516
#define AGS 68
#define SMEM_AGG ((16 * PS + 64 * AGS) * 4)

__device__ __forceinline__ int head_col(int h, int c) {
    if (c < 16) return h * 16 + c;
    if (c < 40) return 128 + h * 24 + (c - 16);
    return 320 + h * 20 + (c - 40);
}

__global__ void __launch_bounds__(256, 3) k_agg(
    const float* __restrict__ node_feat, float* __restrict__ out)
{
    extern __shared__ float smA[];
    float* sP = smA;              // [16][PS]
    float* sV = smA + 16 * PS;    // [64][AGS]

    int tid = threadIdx.x;
    int h = blockIdx.x >> 5, rt = blockIdx.x & 31;
    int r0 = rt * 16;

    const float* Pb = g_P + (size_t)h * (N_NODES * N_NODES);
    for (int i = tid; i < 2048; i += 256) {
        int r_l = i >> 7, s4 = i & 127;
        float4 v = *(const float4*)&Pb[(size_t)(r0 + r_l) * 512 + s4 * 4];
        *(float4*)&sP[r_l * PS + s4 * 4] = v;
    }
    __syncthreads();

    int w = tid >> 5, lane = tid & 31;

#pragma unroll
    for (int rr = 0; rr < 2; rr++) {
        float* row = &sP[(w * 2 + rr) * PS];
        float v[16];
        float mx = -1e30f;
#pragma unroll
        for (int k = 0; k < 16; k++) { v[k] = row[lane + 32 * k]; mx = fmaxf(mx, v[k]); }
#pragma unroll
        for (int o = 16; o; o >>= 1) mx = fmaxf(mx, __shfl_xor_sync(0xffffffffu, mx, o));
        float sum = 0.f;
#pragma unroll
        for (int k = 0; k < 16; k++) { v[k] = __expf(v[k] - mx); sum += v[k]; }
#pragma unroll
        for (int o = 16; o; o >>= 1) sum += __shfl_xor_sync(0xffffffffu, sum, o);
        float rinv = __fdividef(1.0f, sum);
#pragma unroll
        for (int k = 0; k < 16; k++) row[lane + 32 * k] = f2tf32f(v[k] * rinv);
    }

    int g = lane >> 2, t = lane & 3;
    float acc[4] = {0.f, 0.f, 0.f, 0.f};

    for (int kc = 0; kc < 8; kc++) {
        __syncthreads();
        for (int i = tid; i < 4096; i += 256) {
            int c_l = i >> 6, s_l = i & 63;
            float val = 0.f;
            if (c_l < 60) val = g_vmT[(size_t)head_col(h, c_l) * 512 + kc * 64 + s_l];
            sV[c_l * AGS + s_l] = f2tf32f(val);
        }
        __syncthreads();
#pragma unroll
        for (int ksi = 0; ksi < 8; ksi++) {
            int colg = kc * 64 + ksi * 8 + t;
            unsigned a[4];
            a[0] = __float_as_uint(sP[g * PS + colg]);
            a[1] = __float_as_uint(sP[(g + 8) * PS + colg]);
            a[2] = __float_as_uint(sP[g * PS + colg + 4]);
            a[3] = __float_as_uint(sP[(g + 8) * PS + colg + 4]);
            int col = ksi * 8 + t;
            unsigned b0 = __float_as_uint(sV[(w * 8 + g) * AGS + col]);
            unsigned b1 = __float_as_uint(sV[(w * 8 + g) * AGS + col + 4]);
            mma_tf32(acc, a, b0, b1);
        }
    }

    int c0 = w * 8 + 2 * t;
    if (c0 < 60) {
        int cg = head_col(h, c0);
        int rg0 = r0 + g, rg1 = rg0 + 8;
        float2 nf0 = *(const float2*)&node_feat[(size_t)rg0 * 480 + cg];
        float2 nf1 = *(const float2*)&node_feat[(size_t)rg1 * 480 + cg];
        *(float2*)&out[(size_t)rg0 * 480 + cg] = make_float2(nf0.x + acc[0], nf0.y + acc[1]);
        *(float2*)&out[(size_t)rg1 * 480 + cg] = make_float2(nf1.x + acc[2], nf1.y + acc[3]);
    }
}

// ================= launch =================
extern "C" void kernel_launch(void* const* d_in, const int* in_sizes, int n_in,
                              void* d_out, int out_size)
{
    const float* node_feat = (const float*)d_in[0];
    const float* edge_attr = (const float*)d_in[1];
    const float* edge_sh   = (const float*)d_in[2];
    const float* Wq0 = (const float*)d_in[3];
    const float* Wq1 = (const float*)d_in[4];
    const float* Wq2 = (const float*)d_in[5];
    const float* Wk0 = (const float*)d_in[6];
    const float* Wk1 = (const float*)d_in[7];
    const float* Wk2 = (const float*)d_in[8];
    const float* Wv0 = (const float*)d_in[9];
    const float* Wv1 = (const float*)d_in[10];
    const float* Wv2 = (const float*)d_in[11];
    const float* mW1 = (const float*)d_in[12];
    const float* mb1 = (const float*)d_in[13];
    const float* mW2 = (const float*)d_in[14];
    const float* mb2 = (const float*)d_in[15];
    const float* mW3 = (const float*)d_in[16];
    const float* mb3 = (const float*)d_in[17];
    float* out = (float*)d_out;

    cudaFuncSetAttribute(k_mlp, cudaFuncAttributeMaxDynamicSharedMemorySize, SMEM_MLP);
    cudaFuncSetAttribute(k_agg, cudaFuncAttributeMaxDynamicSharedMemorySize, SMEM_AGG);

    k_prep_w<<<1, 256>>>(mW1, mW2);
    k_node<<<dim3(128, 4), 256>>>(node_feat, Wq0, Wq1, Wq2, Wk0, Wk1, Wk2, Wv0, Wv1, Wv2, mW1);
    k_prep_ab<<<512, 256>>>();
    k_XB<<<2048, 256>>>(edge_sh, mb1);
    k_logit<<<512, 256>>>();
    k_mlp<<<2048, 256, SMEM_MLP>>>(edge_attr, edge_sh, mb2, mW3, mb3);
    k_agg<<<256, 256, SMEM_AGG>>>(node_feat, out);
}